// round 15
// baseline (speedup 1.0000x reference)
#include <cuda_runtime.h>
#include <cuda_bf16.h>
#include <cuda_fp16.h>
#include <cstdint>

typedef unsigned long long ull;

// ---------------- problem constants ----------------
#define BATCH   4096
#define LSEQ    50
#define CIN     128
#define CO1     50
#define K1      9
#define LO1     42
#define KKTOT   1152
#define KCH     128     // conv1 k-chunk (9 chunks == 9 taps)
#define NCH     9
#define CH2     64
#define CI2     42
#define K2      3
#define LO2     48
#define PK      144
#define NCAPS   384
#define NO      5
#define DIMD    16
#define PAIRS   1920

// ---------------- smem layout ----------------
// Byte overlay region [0, 61440):
//   phase1: Xh [0,15232)B 56x136h ; WB0 [15232,32640)B ; WB1 [32640,50048)B
//   phase2: PWH 64x152h (overlays X/WB0)
//   phase3+: UH2 half2[15360] = [o*8+dp][c]
#define XH_OFF    0
#define XH_STR    136
#define WB0H      7616
#define WB1H      16320
#define WBSTR     136
#define PWH_OFF   0
#define PWSTR     152
#define HPH_OFF   30720        // halves; 50 x 56
#define HPH_STR   56
// float indices:
#define U_OFF     16760        // 384 x 9
#define U_STRIDE  9
#define BB_OFF    20216
#define CC_OFF    22136
#define S_OFF     24056
#define SC_OFF    24136
#define V_OFF     24144
#define SP_OFF    24224        // 160: s-scan partials [h(2)][rc(40)][j(2)]
#define SMEM_FLOATS 24384
#define SMEM_BYTES  (SMEM_FLOATS * 4)

// device-global scratch
__device__ __half g_w16[NCH * 64 * WBSTR];     // conv1 w: [tap][co 64][136h]
__device__ __half g_pw16[CH2 * PWSTR];         // pconv w: [ch][152h]
__device__ __half g_Wt[PAIRS * DIMD * 8];      // routing W fp16 interleaved

__device__ __forceinline__ void mma_f16(float c[4], unsigned a0, unsigned a1,
                                        unsigned a2, unsigned a3,
                                        unsigned b0, unsigned b1) {
    asm volatile(
        "mma.sync.aligned.m16n8k16.row.col.f32.f16.f16.f32 "
        "{%0,%1,%2,%3}, {%4,%5,%6,%7}, {%8,%9}, {%0,%1,%2,%3};"
        : "+f"(c[0]), "+f"(c[1]), "+f"(c[2]), "+f"(c[3])
        : "r"(a0), "r"(a1), "r"(a2), "r"(a3), "r"(b0), "r"(b1));
}

__device__ __forceinline__ void ldsm_x4(unsigned &r0, unsigned &r1,
                                        unsigned &r2, unsigned &r3, unsigned addr) {
    asm volatile("ldmatrix.sync.aligned.m8n8.x4.shared.b16 {%0,%1,%2,%3}, [%4];"
                 : "=r"(r0), "=r"(r1), "=r"(r2), "=r"(r3) : "r"(addr));
}

__device__ __forceinline__ void cp16(unsigned smem_addr, const void* gptr) {
    asm volatile("cp.async.cg.shared.global [%0], [%1], 16;"
                 :: "r"(smem_addr), "l"(gptr));
}
#define CP_COMMIT() asm volatile("cp.async.commit_group;")
#define CP_WAIT(n)  asm volatile("cp.async.wait_group %0;" :: "n"(n))

// packed f32x2 helpers (Blackwell FFMA2)
__device__ __forceinline__ ull pack2(float x, float y) {
    ull r;
    asm("mov.b64 %0, {%1, %2};" : "=l"(r) : "f"(x), "f"(y));
    return r;
}
__device__ __forceinline__ void unpack2(ull v, float &x, float &y) {
    asm("mov.b64 {%0, %1}, %2;" : "=f"(x), "=f"(y) : "l"(v));
}
__device__ __forceinline__ ull fma2(ull a, ull b, ull c) {
    ull d;
    asm("fma.rn.f32x2 %0, %1, %2, %3;" : "=l"(d) : "l"(a), "l"(b), "l"(c));
    return d;
}

// ---------------- prologue: weight reorder / convert ----------------
__global__ void reorder_weights(const float* __restrict__ w1,
                                const float* __restrict__ w2,
                                const float* __restrict__ W) {
    int i = blockIdx.x * 256 + threadIdx.x;
    if (i < NCH * 64 * WBSTR) {
        int ch = i / (64 * WBSTR);
        int r  = i % (64 * WBSTR);
        int co = r / WBSTR, j = r % WBSTR;
        float v = 0.f;
        if (j < 128 && co < CO1)
            v = w1[co * KKTOT + j * K1 + ch];
        g_w16[i] = __float2half(v);
    }
    if (i < CH2 * PWSTR) {
        int chn = i / PWSTR, kk = i % PWSTR;
        float v = 0.f;
        if (kk < PK) {
            int kb = kk / 48, ci = kk % 48;
            if (ci < CI2)
                v = w2[chn * (CI2 * K2) + ci * K2 + kb];
        }
        g_pw16[i] = __float2half(v);
    }
    if (i < PAIRS * DIMD * 8) {
        int jl = i & 7;
        int q  = i >> 3;
        int ln = q & 31;
        int t  = q >> 5;
        int h  = t & 1;
        int t2 = t >> 1;
        int dp = t2 & 7;
        int pg = t2 >> 3;
        int jj = h * 8 + jl;
        int ii = jj >> 1;
        int ds = jj & 1;
        int p  = pg * 32 + ln;
        g_Wt[i] = __float2half(W[(p * 16 + 2 * dp + ds) * 8 + ii]);
    }
}

// ---------------- fused main kernel: 1 block = 1 sample, 2 blocks/SM ----------------
__global__ __launch_bounds__(512, 2)
void caps_main(const float* __restrict__ x,
               const float* __restrict__ c1b,
               const float* __restrict__ p2b,
               float* __restrict__ out) {
    extern __shared__ float S[];
    __half*  Sh  = (__half*)S;
    __half2* Sh2 = (__half2*)S;
    const int b    = blockIdx.x;
    const int tid  = threadIdx.x;
    const int lane = tid & 31;
    const int warp = tid >> 5;
    const unsigned smem_u32 = (unsigned)__cvta_generic_to_shared(S);

    // ldmatrix lane selectors
    const int aRowSel = (lane & 7) + ((lane >> 3) & 1) * 8;
    const int aColSel = (lane >> 4) * 8;
    const int bRowSel = (lane & 7) + (lane >> 4) * 8;
    const int bColSel = ((lane >> 3) & 1) * 8;

    // ---- phase 0: cp.async conv chunk 0, stage x->fp16, zero scratch ----
    {
        const uint4* src = (const uint4*)g_w16;   // chunk = 1088 x 16B
        #pragma unroll
        for (int j = 0; j < 3; j++) {
            int i = tid + j * 512;
            if (i < 1088) cp16(smem_u32 + WB0H * 2 + i * 16, src + i);
        }
        CP_COMMIT();
    }
    const float4* xb = (const float4*)(x + (size_t)b * (LSEQ * CIN));
    for (int i = tid; i < (LSEQ * CIN) / 4; i += 512) {
        float4 v = __ldg(xb + i);
        __half2 h0 = __floats2half2_rn(v.x, v.y);
        __half2 h1 = __floats2half2_rn(v.z, v.w);
        int l = i >> 5, c4 = i & 31;
        uint2 pk;
        pk.x = *(unsigned*)&h0; pk.y = *(unsigned*)&h1;
        *(uint2*)&Sh[XH_OFF + l * XH_STR + c4 * 4] = pk;
    }
    for (int i = tid; i < (6 * XH_STR) / 2; i += 512)
        *(unsigned*)&Sh[XH_OFF + 50 * XH_STR + i * 2] = 0u;
    for (int i = tid; i < (CO1 * HPH_STR) / 2; i += 512)
        *(unsigned*)&Sh[HPH_OFF + i * 2] = 0u;
    // (BB init removed: it-0 b-update stores directly)

    // ---- phase 1: conv1 fp16 mma + ldmatrix: C[l(48), co(64)], 12 warps ----
    const int mt  = warp >> 2;        // 0..2
    const int ntg = warp & 3;
    const int gID = lane >> 2;
    const int tig = lane & 3;
    float acc0[4] = {0, 0, 0, 0};
    float acc1[4] = {0, 0, 0, 0};

    for (int ch = 0; ch < NCH; ch++) {
        __syncthreads();
        if (ch + 1 < NCH) {
            const uint4* src = (const uint4*)g_w16 + (ch + 1) * 1088;
            int wbh = ((ch + 1) & 1) ? WB1H : WB0H;
            #pragma unroll
            for (int j = 0; j < 3; j++) {
                int i = tid + j * 512;
                if (i < 1088) cp16(smem_u32 + wbh * 2 + i * 16, src + i);
            }
            CP_COMMIT();
            CP_WAIT(1);
        } else {
            CP_WAIT(0);
        }
        __syncthreads();
        if (warp < 12) {
            const int wbh = (ch & 1) ? WB1H : WB0H;
            unsigned aBase = smem_u32 +
                2 * (XH_OFF + (mt * 16 + aRowSel + ch) * XH_STR + aColSel);
            unsigned bBase = smem_u32 +
                2 * (wbh + (ntg * 16 + bRowSel) * WBSTR + bColSel);
            #pragma unroll
            for (int ks = 0; ks < KCH / 16; ks++) {
                unsigned a0, a1, a2, a3, b0, b1, b2, b3;
                ldsm_x4(a0, a1, a2, a3, aBase + ks * 32);
                ldsm_x4(b0, b1, b2, b3, bBase + ks * 32);
                mma_f16(acc0, a0, a1, a2, a3, b0, b1);
                mma_f16(acc1, a0, a1, a2, a3, b2, b3);
            }
        }
    }
    __syncthreads();   // conv compute done; X/WB regions free

    // issue pconv weight staging NOW (overlaps conv epilogue)
    for (int j = 0; j < 3; j++) {
        int i = tid + j * 512;
        if (i < (CH2 * PWSTR) / 8) {
            cp16(smem_u32 + PWH_OFF * 2 + i * 16, (const uint4*)g_pw16 + i);
        }
    }
    CP_COMMIT();

    // epilogue: bias + relu -> HpH[co][l]
    if (warp < 12) {
        int m_lo = mt * 16 + gID, m_hi = m_lo + 8;
        #pragma unroll
        for (int t = 0; t < 2; t++) {
            float* a = (t == 0) ? acc0 : acc1;
            #pragma unroll
            for (int q = 0; q < 2; q++) {
                int n = ntg * 16 + t * 8 + 2 * tig + q;
                if (n < CO1) {
                    float bias = __ldg(&c1b[n]);
                    if (m_lo < LO1)
                        Sh[HPH_OFF + n * HPH_STR + m_lo] = __float2half(fmaxf(a[q] + bias, 0.f));
                    if (m_hi < LO1)
                        Sh[HPH_OFF + n * HPH_STR + m_hi] = __float2half(fmaxf(a[q + 2] + bias, 0.f));
                }
            }
        }
    }
    CP_WAIT(0);
    __syncthreads();   // HP + PWH visible

    // ---- phase 2: pconv fp16 mma + ldmatrix: C[pos(48), ch(64)], 12 warps ----
    {
        float pacc0[4] = {0, 0, 0, 0};
        float pacc1[4] = {0, 0, 0, 0};
        if (warp < 12) {
            unsigned bBase = smem_u32 +
                2 * (PWH_OFF + (ntg * 16 + bRowSel) * PWSTR + bColSel);
            #pragma unroll
            for (int ks = 0; ks < PK / 16; ks++) {
                int kb = (ks * 16) / 48, cb = (ks * 16) % 48;
                unsigned aAddr = smem_u32 +
                    2 * (HPH_OFF + (mt * 16 + aRowSel + kb) * HPH_STR + cb + aColSel);
                unsigned a0, a1, a2, a3, b0, b1, b2, b3;
                ldsm_x4(a0, a1, a2, a3, aAddr);
                ldsm_x4(b0, b1, b2, b3, bBase + ks * 32);
                mma_f16(pacc0, a0, a1, a2, a3, b0, b1);
                mma_f16(pacc1, a0, a1, a2, a3, b2, b3);
            }
            int m_lo = mt * 16 + gID, m_hi = m_lo + 8;
            #pragma unroll
            for (int t = 0; t < 2; t++) {
                float* a = (t == 0) ? pacc0 : pacc1;
                #pragma unroll
                for (int q = 0; q < 2; q++) {
                    int n = ntg * 16 + t * 8 + 2 * tig + q;
                    float bias = __ldg(&p2b[n]);
                    int lin0 = n * LO2 + m_lo;
                    int lin1 = n * LO2 + m_hi;
                    S[U_OFF + (lin0 >> 3) * U_STRIDE + (lin0 & 7)] = a[q] + bias;
                    S[U_OFF + (lin1 >> 3) * U_STRIDE + (lin1 & 7)] = a[q + 2] + bias;
                }
            }
        }
    }
    __syncthreads();
    if (tid < NCAPS) {
        float vv[8], sq = 0.f;
        #pragma unroll
        for (int i = 0; i < 8; i++) { vv[i] = S[U_OFF + tid * U_STRIDE + i]; sq += vv[i] * vv[i]; }
        float sc = sq / ((1.f + sq) * (sqrtf(sq) + 1e-8f));
        #pragma unroll
        for (int i = 0; i < 8; i++) S[U_OFF + tid * U_STRIDE + i] = vv[i] * sc;
    }
    __syncthreads();

    // ---- phase 3: u_hat -> UH2[o][dp][c] via packed FFMA2 ----
    for (int p = tid; p < PAIRS; p += 512) {
        int c = p % NCAPS;
        int o = p / NCAPS;
        ull u2[8];
        #pragma unroll
        for (int i = 0; i < 8; i++) {
            float ui = S[U_OFF + c * U_STRIDE + i];
            u2[i] = pack2(ui, ui);
        }
        const uint4* wp = (const uint4*)g_Wt + (p >> 5) * 512 + (p & 31);
        #pragma unroll 4
        for (int dp = 0; dp < 8; dp++) {
            uint4 r0 = __ldg(wp + dp * 64);
            uint4 r1 = __ldg(wp + dp * 64 + 32);
            ull acc = 0;
            float2 f;
            f = __half22float2(*(__half2*)&r0.x); acc = fma2(*(ull*)&f, u2[0], acc);
            f = __half22float2(*(__half2*)&r0.y); acc = fma2(*(ull*)&f, u2[1], acc);
            f = __half22float2(*(__half2*)&r0.z); acc = fma2(*(ull*)&f, u2[2], acc);
            f = __half22float2(*(__half2*)&r0.w); acc = fma2(*(ull*)&f, u2[3], acc);
            f = __half22float2(*(__half2*)&r1.x); acc = fma2(*(ull*)&f, u2[4], acc);
            f = __half22float2(*(__half2*)&r1.y); acc = fma2(*(ull*)&f, u2[5], acc);
            f = __half22float2(*(__half2*)&r1.z); acc = fma2(*(ull*)&f, u2[6], acc);
            f = __half22float2(*(__half2*)&r1.w); acc = fma2(*(ull*)&f, u2[7], acc);
            float s0, s1;
            unpack2(acc, s0, s1);
            Sh2[(o * 8 + dp) * NCAPS + c] = __floats2half2_rn(s0, s1);
        }
    }
    __syncthreads();

    // ---- phase 4: dynamic routing (it=0 softmax skipped: c == 0.2) ----
    for (int it = 0; it < 3; it++) {
        if (it) {
            if (tid < NCAPS) {
                float bv[NO], m = -1e30f;
                #pragma unroll
                for (int o = 0; o < NO; o++) { bv[o] = S[BB_OFF + o * NCAPS + tid]; m = fmaxf(m, bv[o]); }
                float sum = 0.f;
                #pragma unroll
                for (int o = 0; o < NO; o++) { bv[o] = expf(bv[o] - m); sum += bv[o]; }
                float inv = 1.f / sum;
                #pragma unroll
                for (int o = 0; o < NO; o++) S[CC_OFF + o * NCAPS + tid] = bv[o] * inv;
            }
            __syncthreads();
        }
        // s-scan: 80 balanced half-range tasks over 16 warps (5 rounds x 6 steps)
        for (int task = warp; task < 80; task += 16) {
            int h = task >= 40;
            int rc = task - 40 * h;
            int o = rc >> 3, dp = rc & 7;
            int cbeg = h * 192;
            float a0 = 0.f, a1 = 0.f;
            if (it == 0) {
                #pragma unroll 3
                for (int c = cbeg + lane; c < cbeg + 192; c += 32) {
                    float2 f = __half22float2(Sh2[(o * 8 + dp) * NCAPS + c]);
                    a0 += f.x;
                    a1 += f.y;
                }
            } else {
                #pragma unroll 3
                for (int c = cbeg + lane; c < cbeg + 192; c += 32) {
                    float cc = S[CC_OFF + o * NCAPS + c];
                    float2 f = __half22float2(Sh2[(o * 8 + dp) * NCAPS + c]);
                    a0 += cc * f.x;
                    a1 += cc * f.y;
                }
            }
            #pragma unroll
            for (int off = 16; off; off >>= 1) {
                a0 += __shfl_xor_sync(0xffffffffu, a0, off);
                a1 += __shfl_xor_sync(0xffffffffu, a1, off);
            }
            if (lane == 0) {
                S[SP_OFF + (h * 40 + rc) * 2]     = a0;
                S[SP_OFF + (h * 40 + rc) * 2 + 1] = a1;
            }
        }
        __syncthreads();
        // combine partials -> s
        if (tid < 80) {
            int j = tid & 1, rc = tid >> 1;
            float v = S[SP_OFF + rc * 2 + j] + S[SP_OFF + (40 + rc) * 2 + j];
            if (it == 0) v *= 0.2f;
            int o = rc >> 3, dp = rc & 7;
            S[S_OFF + o * DIMD + 2 * dp + j] = v;
        }
        __syncthreads();
        if (tid < NO) {
            float sq = 0.f;
            #pragma unroll
            for (int d = 0; d < DIMD; d++) { float t = S[S_OFF + tid * DIMD + d]; sq += t * t; }
            S[SC_OFF + tid] = sq / ((1.f + sq) * (sqrtf(sq) + 1e-8f));
        }
        __syncthreads();
        if (it == 2) break;
        if (tid < NO * DIMD) S[V_OFF + tid] = S[S_OFF + tid] * S[SC_OFF + (tid >> 4)];
        __syncthreads();
        for (int p = tid; p < PAIRS; p += 512) {
            int o = p / NCAPS;
            int c = p % NCAPS;
            const ull* v2p = (const ull*)&S[V_OFF + o * DIMD];
            ull acc = 0;
            #pragma unroll
            for (int j = 0; j < 8; j++) {
                float2 f = __half22float2(Sh2[(o * 8 + j) * NCAPS + c]);
                acc = fma2(*(ull*)&f, v2p[j], acc);
            }
            float lo, hi;
            unpack2(acc, lo, hi);
            if (it == 0) S[BB_OFF + p] = lo + hi;     // BB was never initialized
            else         S[BB_OFF + p] += lo + hi;
        }
        __syncthreads();
    }
    if (tid < NO * DIMD)
        out[(size_t)b * (NO * DIMD) + tid] = S[S_OFF + tid] * S[SC_OFF + (tid >> 4)];
}

// ---------------- launch ----------------
extern "C" void kernel_launch(void* const* d_in, const int* in_sizes, int n_in,
                              void* d_out, int out_size) {
    const float* x       = (const float*)d_in[0];
    const float* conv1_w = (const float*)d_in[1];
    const float* conv1_b = (const float*)d_in[2];
    const float* pconv_w = (const float*)d_in[3];
    const float* pconv_b = (const float*)d_in[4];
    const float* W       = (const float*)d_in[5];
    float* out = (float*)d_out;

    cudaFuncSetAttribute(caps_main, cudaFuncAttributeMaxDynamicSharedMemorySize, SMEM_BYTES);

    reorder_weights<<<(PAIRS * DIMD * 8 + 255) / 256, 256>>>(conv1_w, pconv_w, W);
    caps_main<<<BATCH, 512, SMEM_BYTES>>>(x, conv1_b, pconv_b, out);
}

// round 16
// speedup vs baseline: 1.1181x; 1.1181x over previous
#include <cuda_runtime.h>
#include <cuda_bf16.h>
#include <cuda_fp16.h>
#include <cstdint>

typedef unsigned long long ull;

// ---------------- problem constants ----------------
#define BATCH   4096
#define LSEQ    50
#define CIN     128
#define CO1     50
#define K1      9
#define LO1     42
#define KKTOT   1152
#define KCH     128     // conv1 k-chunk (9 chunks == 9 taps)
#define NCH     9
#define CH2     64
#define CI2     42
#define K2      3
#define LO2     48
#define PK      144
#define NCAPS   384
#define NO      5
#define DIMD    16
#define PAIRS   1920

// ---------------- smem layout (R14 map) ----------------
// Byte overlay region [0, 61440):
//   phase1: Xh [0,15232)B 56x136h ; WB0 [15232,32640)B ; WB1 [32640,50048)B
//   phase2: PWH 64x152h (overlays X/WB0)
//   phase3+: UH2 half2[15360] = [o*8+dp][c]
#define XH_OFF    0
#define XH_STR    136
#define WB0H      7616
#define WB1H      16320
#define WBSTR     136
#define PWH_OFF   0
#define PWSTR     152
#define HPH_OFF   30720        // halves; 50 x 56
#define HPH_STR   56
// float indices:
#define U_OFF     16760        // 384 x 9
#define U_STRIDE  9
#define BB_OFF    20216
#define CC_OFF    22136
#define S_OFF     24056
#define SC_OFF    24136
#define V_OFF     24144
#define SMEM_FLOATS 24224
#define SMEM_BYTES  (SMEM_FLOATS * 4)

// device-global scratch
__device__ __half g_w16[NCH * 64 * WBSTR];     // conv1 w: [tap][co 64][136h]
__device__ __half g_pw16[CH2 * PWSTR];         // pconv w: [ch][152h]
__device__ __half g_Wt[PAIRS * DIMD * 8];      // routing W fp16 interleaved

__device__ __forceinline__ void mma_f16(float c[4], unsigned a0, unsigned a1,
                                        unsigned a2, unsigned a3,
                                        unsigned b0, unsigned b1) {
    asm volatile(
        "mma.sync.aligned.m16n8k16.row.col.f32.f16.f16.f32 "
        "{%0,%1,%2,%3}, {%4,%5,%6,%7}, {%8,%9}, {%0,%1,%2,%3};"
        : "+f"(c[0]), "+f"(c[1]), "+f"(c[2]), "+f"(c[3])
        : "r"(a0), "r"(a1), "r"(a2), "r"(a3), "r"(b0), "r"(b1));
}

__device__ __forceinline__ void ldsm_x4(unsigned &r0, unsigned &r1,
                                        unsigned &r2, unsigned &r3, unsigned addr) {
    asm volatile("ldmatrix.sync.aligned.m8n8.x4.shared.b16 {%0,%1,%2,%3}, [%4];"
                 : "=r"(r0), "=r"(r1), "=r"(r2), "=r"(r3) : "r"(addr));
}

__device__ __forceinline__ void cp16(unsigned smem_addr, const void* gptr) {
    asm volatile("cp.async.cg.shared.global [%0], [%1], 16;"
                 :: "r"(smem_addr), "l"(gptr));
}
#define CP_COMMIT() asm volatile("cp.async.commit_group;")
#define CP_WAIT(n)  asm volatile("cp.async.wait_group %0;" :: "n"(n))

// packed f32x2 helpers (Blackwell FFMA2)
__device__ __forceinline__ ull pack2(float x, float y) {
    ull r;
    asm("mov.b64 %0, {%1, %2};" : "=l"(r) : "f"(x), "f"(y));
    return r;
}
__device__ __forceinline__ void unpack2(ull v, float &x, float &y) {
    asm("mov.b64 {%0, %1}, %2;" : "=f"(x), "=f"(y) : "l"(v));
}
__device__ __forceinline__ ull fma2(ull a, ull b, ull c) {
    ull d;
    asm("fma.rn.f32x2 %0, %1, %2, %3;" : "=l"(d) : "l"(a), "l"(b), "l"(c));
    return d;
}

// ---------------- prologue: weight reorder / convert ----------------
__global__ void reorder_weights(const float* __restrict__ w1,
                                const float* __restrict__ w2,
                                const float* __restrict__ W) {
    int i = blockIdx.x * 256 + threadIdx.x;
    if (i < NCH * 64 * WBSTR) {
        int ch = i / (64 * WBSTR);
        int r  = i % (64 * WBSTR);
        int co = r / WBSTR, j = r % WBSTR;
        float v = 0.f;
        if (j < 128 && co < CO1)
            v = w1[co * KKTOT + j * K1 + ch];
        g_w16[i] = __float2half(v);
    }
    if (i < CH2 * PWSTR) {
        int chn = i / PWSTR, kk = i % PWSTR;
        float v = 0.f;
        if (kk < PK) {
            int kb = kk / 48, ci = kk % 48;
            if (ci < CI2)
                v = w2[chn * (CI2 * K2) + ci * K2 + kb];
        }
        g_pw16[i] = __float2half(v);
    }
    if (i < PAIRS * DIMD * 8) {
        int jl = i & 7;
        int q  = i >> 3;
        int ln = q & 31;
        int t  = q >> 5;
        int h  = t & 1;
        int t2 = t >> 1;
        int dp = t2 & 7;
        int pg = t2 >> 3;
        int jj = h * 8 + jl;
        int ii = jj >> 1;
        int ds = jj & 1;
        int p  = pg * 32 + ln;
        g_Wt[i] = __float2half(W[(p * 16 + 2 * dp + ds) * 8 + ii]);
    }
}

// ---------------- fused main kernel: 1 block = 1 sample, 2 blocks/SM ----------------
__global__ __launch_bounds__(512, 2)
void caps_main(const float* __restrict__ x,
               const float* __restrict__ c1b,
               const float* __restrict__ p2b,
               float* __restrict__ out) {
    extern __shared__ float S[];
    __half*  Sh  = (__half*)S;
    __half2* Sh2 = (__half2*)S;
    const int b    = blockIdx.x;
    const int tid  = threadIdx.x;
    const int lane = tid & 31;
    const int warp = tid >> 5;
    const unsigned smem_u32 = (unsigned)__cvta_generic_to_shared(S);

    // ldmatrix lane selectors
    const int aRowSel = (lane & 7) + ((lane >> 3) & 1) * 8;
    const int aColSel = (lane >> 4) * 8;
    const int bRowSel = (lane & 7) + (lane >> 4) * 8;
    const int bColSel = ((lane >> 3) & 1) * 8;

    // ---- phase 0: cp.async conv chunk 0, stage x->fp16, zero scratch ----
    {
        const uint4* src = (const uint4*)g_w16;   // chunk = 1088 x 16B
        #pragma unroll
        for (int j = 0; j < 3; j++) {
            int i = tid + j * 512;
            if (i < 1088) cp16(smem_u32 + WB0H * 2 + i * 16, src + i);
        }
        CP_COMMIT();
    }
    const float4* xb = (const float4*)(x + (size_t)b * (LSEQ * CIN));
    for (int i = tid; i < (LSEQ * CIN) / 4; i += 512) {
        float4 v = __ldg(xb + i);
        __half2 h0 = __floats2half2_rn(v.x, v.y);
        __half2 h1 = __floats2half2_rn(v.z, v.w);
        int l = i >> 5, c4 = i & 31;
        uint2 pk;
        pk.x = *(unsigned*)&h0; pk.y = *(unsigned*)&h1;
        *(uint2*)&Sh[XH_OFF + l * XH_STR + c4 * 4] = pk;
    }
    for (int i = tid; i < (6 * XH_STR) / 2; i += 512)
        *(unsigned*)&Sh[XH_OFF + 50 * XH_STR + i * 2] = 0u;
    for (int i = tid; i < (CO1 * HPH_STR) / 2; i += 512)
        *(unsigned*)&Sh[HPH_OFF + i * 2] = 0u;
    // (BB init removed: it-0 b-update stores directly)

    // ---- phase 1: conv1 fp16 mma + ldmatrix: C[l(48), co(64)], 12 warps ----
    const int mt  = warp >> 2;        // 0..2
    const int ntg = warp & 3;
    const int gID = lane >> 2;
    const int tig = lane & 3;
    float acc0[4] = {0, 0, 0, 0};
    float acc1[4] = {0, 0, 0, 0};

    for (int ch = 0; ch < NCH; ch++) {
        __syncthreads();
        if (ch + 1 < NCH) {
            const uint4* src = (const uint4*)g_w16 + (ch + 1) * 1088;
            int wbh = ((ch + 1) & 1) ? WB1H : WB0H;
            #pragma unroll
            for (int j = 0; j < 3; j++) {
                int i = tid + j * 512;
                if (i < 1088) cp16(smem_u32 + wbh * 2 + i * 16, src + i);
            }
            CP_COMMIT();
            CP_WAIT(1);
        } else {
            CP_WAIT(0);
        }
        __syncthreads();
        if (warp < 12) {
            const int wbh = (ch & 1) ? WB1H : WB0H;
            unsigned aBase = smem_u32 +
                2 * (XH_OFF + (mt * 16 + aRowSel + ch) * XH_STR + aColSel);
            unsigned bBase = smem_u32 +
                2 * (wbh + (ntg * 16 + bRowSel) * WBSTR + bColSel);
            #pragma unroll
            for (int ks = 0; ks < KCH / 16; ks++) {
                unsigned a0, a1, a2, a3, b0, b1, b2, b3;
                ldsm_x4(a0, a1, a2, a3, aBase + ks * 32);
                ldsm_x4(b0, b1, b2, b3, bBase + ks * 32);
                mma_f16(acc0, a0, a1, a2, a3, b0, b1);
                mma_f16(acc1, a0, a1, a2, a3, b2, b3);
            }
        }
    }
    __syncthreads();   // conv compute done; X/WB regions free

    // issue pconv weight staging now (overlaps conv epilogue)
    {
        #pragma unroll
        for (int j = 0; j < 3; j++) {
            int i = tid + j * 512;
            if (i < (CH2 * PWSTR) / 8)
                cp16(smem_u32 + PWH_OFF * 2 + i * 16, (const uint4*)g_pw16 + i);
        }
        CP_COMMIT();
    }

    // epilogue: bias + relu -> HpH[co][l]
    if (warp < 12) {
        int m_lo = mt * 16 + gID, m_hi = m_lo + 8;
        #pragma unroll
        for (int t = 0; t < 2; t++) {
            float* a = (t == 0) ? acc0 : acc1;
            #pragma unroll
            for (int q = 0; q < 2; q++) {
                int n = ntg * 16 + t * 8 + 2 * tig + q;
                if (n < CO1) {
                    float bias = __ldg(&c1b[n]);
                    if (m_lo < LO1)
                        Sh[HPH_OFF + n * HPH_STR + m_lo] = __float2half(fmaxf(a[q] + bias, 0.f));
                    if (m_hi < LO1)
                        Sh[HPH_OFF + n * HPH_STR + m_hi] = __float2half(fmaxf(a[q + 2] + bias, 0.f));
                }
            }
        }
    }
    CP_WAIT(0);
    __syncthreads();   // HP + PWH visible

    // ---- phase 2: pconv fp16 mma + ldmatrix: C[pos(48), ch(64)], 12 warps ----
    {
        float pacc0[4] = {0, 0, 0, 0};
        float pacc1[4] = {0, 0, 0, 0};
        if (warp < 12) {
            unsigned bBase = smem_u32 +
                2 * (PWH_OFF + (ntg * 16 + bRowSel) * PWSTR + bColSel);
            #pragma unroll
            for (int ks = 0; ks < PK / 16; ks++) {
                int kb = (ks * 16) / 48, cb = (ks * 16) % 48;
                unsigned aAddr = smem_u32 +
                    2 * (HPH_OFF + (mt * 16 + aRowSel + kb) * HPH_STR + cb + aColSel);
                unsigned a0, a1, a2, a3, b0, b1, b2, b3;
                ldsm_x4(a0, a1, a2, a3, aAddr);
                ldsm_x4(b0, b1, b2, b3, bBase + ks * 32);
                mma_f16(pacc0, a0, a1, a2, a3, b0, b1);
                mma_f16(pacc1, a0, a1, a2, a3, b2, b3);
            }
            int m_lo = mt * 16 + gID, m_hi = m_lo + 8;
            #pragma unroll
            for (int t = 0; t < 2; t++) {
                float* a = (t == 0) ? pacc0 : pacc1;
                #pragma unroll
                for (int q = 0; q < 2; q++) {
                    int n = ntg * 16 + t * 8 + 2 * tig + q;
                    float bias = __ldg(&p2b[n]);
                    int lin0 = n * LO2 + m_lo;
                    int lin1 = n * LO2 + m_hi;
                    S[U_OFF + (lin0 >> 3) * U_STRIDE + (lin0 & 7)] = a[q] + bias;
                    S[U_OFF + (lin1 >> 3) * U_STRIDE + (lin1 & 7)] = a[q + 2] + bias;
                }
            }
        }
    }
    __syncthreads();
    if (tid < NCAPS) {
        float vv[8], sq = 0.f;
        #pragma unroll
        for (int i = 0; i < 8; i++) { vv[i] = S[U_OFF + tid * U_STRIDE + i]; sq += vv[i] * vv[i]; }
        float sc = sq / ((1.f + sq) * (sqrtf(sq) + 1e-8f));
        #pragma unroll
        for (int i = 0; i < 8; i++) S[U_OFF + tid * U_STRIDE + i] = vv[i] * sc;
    }
    __syncthreads();

    // ---- phase 3: u_hat -> UH2[o][dp][c] via packed FFMA2 ----
    for (int p = tid; p < PAIRS; p += 512) {
        int c = p % NCAPS;
        int o = p / NCAPS;
        ull u2[8];
        #pragma unroll
        for (int i = 0; i < 8; i++) {
            float ui = S[U_OFF + c * U_STRIDE + i];
            u2[i] = pack2(ui, ui);
        }
        const uint4* wp = (const uint4*)g_Wt + (p >> 5) * 512 + (p & 31);
        #pragma unroll 4
        for (int dp = 0; dp < 8; dp++) {
            uint4 r0 = __ldg(wp + dp * 64);
            uint4 r1 = __ldg(wp + dp * 64 + 32);
            ull acc = 0;
            float2 f;
            f = __half22float2(*(__half2*)&r0.x); acc = fma2(*(ull*)&f, u2[0], acc);
            f = __half22float2(*(__half2*)&r0.y); acc = fma2(*(ull*)&f, u2[1], acc);
            f = __half22float2(*(__half2*)&r0.z); acc = fma2(*(ull*)&f, u2[2], acc);
            f = __half22float2(*(__half2*)&r0.w); acc = fma2(*(ull*)&f, u2[3], acc);
            f = __half22float2(*(__half2*)&r1.x); acc = fma2(*(ull*)&f, u2[4], acc);
            f = __half22float2(*(__half2*)&r1.y); acc = fma2(*(ull*)&f, u2[5], acc);
            f = __half22float2(*(__half2*)&r1.z); acc = fma2(*(ull*)&f, u2[6], acc);
            f = __half22float2(*(__half2*)&r1.w); acc = fma2(*(ull*)&f, u2[7], acc);
            float s0, s1;
            unpack2(acc, s0, s1);
            Sh2[(o * 8 + dp) * NCAPS + c] = __floats2half2_rn(s0, s1);
        }
    }
    __syncthreads();

    // ---- phase 4: dynamic routing (it=0 softmax skipped: c == 0.2) ----
    for (int it = 0; it < 3; it++) {
        if (it) {
            if (tid < NCAPS) {
                float bv[NO], m = -1e30f;
                #pragma unroll
                for (int o = 0; o < NO; o++) { bv[o] = S[BB_OFF + o * NCAPS + tid]; m = fmaxf(m, bv[o]); }
                float sum = 0.f;
                #pragma unroll
                for (int o = 0; o < NO; o++) { bv[o] = expf(bv[o] - m); sum += bv[o]; }
                float inv = 1.f / sum;
                #pragma unroll
                for (int o = 0; o < NO; o++) S[CC_OFF + o * NCAPS + tid] = bv[o] * inv;
            }
            __syncthreads();
        }
        for (int comb = warp; comb < NO * 8; comb += 16) {
            int o = comb >> 3, dp = comb & 7;
            float a0 = 0.f, a1 = 0.f;
            if (it == 0) {
                #pragma unroll 4
                for (int c = lane; c < NCAPS; c += 32) {
                    float2 f = __half22float2(Sh2[(o * 8 + dp) * NCAPS + c]);
                    a0 += f.x;
                    a1 += f.y;
                }
                a0 *= 0.2f; a1 *= 0.2f;
            } else {
                #pragma unroll 4
                for (int c = lane; c < NCAPS; c += 32) {
                    float cc = S[CC_OFF + o * NCAPS + c];
                    float2 f = __half22float2(Sh2[(o * 8 + dp) * NCAPS + c]);
                    a0 += cc * f.x;
                    a1 += cc * f.y;
                }
            }
            #pragma unroll
            for (int off = 16; off; off >>= 1) {
                a0 += __shfl_xor_sync(0xffffffffu, a0, off);
                a1 += __shfl_xor_sync(0xffffffffu, a1, off);
            }
            if (lane == 0) {
                S[S_OFF + o * DIMD + 2 * dp]     = a0;
                S[S_OFF + o * DIMD + 2 * dp + 1] = a1;
            }
        }
        __syncthreads();
        if (tid < NO) {
            float sq = 0.f;
            #pragma unroll
            for (int d = 0; d < DIMD; d++) { float t = S[S_OFF + tid * DIMD + d]; sq += t * t; }
            S[SC_OFF + tid] = sq / ((1.f + sq) * (sqrtf(sq) + 1e-8f));
        }
        __syncthreads();
        if (it == 2) break;
        if (tid < NO * DIMD) S[V_OFF + tid] = S[S_OFF + tid] * S[SC_OFF + (tid >> 4)];
        __syncthreads();
        for (int p = tid; p < PAIRS; p += 512) {
            int o = p / NCAPS;
            int c = p % NCAPS;
            const ull* v2p = (const ull*)&S[V_OFF + o * DIMD];
            ull acc = 0;
            #pragma unroll
            for (int j = 0; j < 8; j++) {
                float2 f = __half22float2(Sh2[(o * 8 + j) * NCAPS + c]);
                acc = fma2(*(ull*)&f, v2p[j], acc);
            }
            float lo, hi;
            unpack2(acc, lo, hi);
            if (it == 0) S[BB_OFF + p] = lo + hi;     // BB was never initialized
            else         S[BB_OFF + p] += lo + hi;
        }
        __syncthreads();
    }
    if (tid < NO * DIMD)
        out[(size_t)b * (NO * DIMD) + tid] = S[S_OFF + tid] * S[SC_OFF + (tid >> 4)];
}

// ---------------- launch ----------------
extern "C" void kernel_launch(void* const* d_in, const int* in_sizes, int n_in,
                              void* d_out, int out_size) {
    const float* x       = (const float*)d_in[0];
    const float* conv1_w = (const float*)d_in[1];
    const float* conv1_b = (const float*)d_in[2];
    const float* pconv_w = (const float*)d_in[3];
    const float* pconv_b = (const float*)d_in[4];
    const float* W       = (const float*)d_in[5];
    float* out = (float*)d_out;

    cudaFuncSetAttribute(caps_main, cudaFuncAttributeMaxDynamicSharedMemorySize, SMEM_BYTES);

    reorder_weights<<<(PAIRS * DIMD * 8 + 255) / 256, 256>>>(conv1_w, pconv_w, W);
    caps_main<<<BATCH, 512, SMEM_BYTES>>>(x, conv1_b, pconv_b, out);
}